// round 8
// baseline (speedup 1.0000x reference)
#include <cuda_runtime.h>
#include <cuda_fp16.h>

#define BB 128
#define TT 256
#define KDIM 50
#define KK 2500          // K*K
#define START_TAG 48
#define END_TAG 49
#define NTH 256
#define SLACK 4.0f       // steady-state exp2 args center at -SLACK: keep inside fp16 range

__device__ float g_vec[2][BB][64];   // [dir][seq][tag]: absolute log2 alpha/beta at split
__device__ float g_gold[2][BB];      // gold partial per (dir, seq)
__device__ float g_apart[BB];        // combined per-seq log all-paths (nats)
__device__ float g_gpart[BB];        // combined per-seq gold
__device__ int   g_pair[BB];         // per-pair arrival counters (self-resetting)
__device__ int   g_count = 0;        // global arrival counter (self-resetting)

__device__ __forceinline__ void cp16(void* dst_smem, const void* src) {
    unsigned s = (unsigned)__cvta_generic_to_shared(dst_smem);
    asm volatile("cp.async.cg.shared.global [%0], [%1], 16;\n" :: "r"(s), "l"(src));
}
__device__ __forceinline__ void cp_commit() {
    asm volatile("cp.async.commit_group;\n");
}
template <int N>
__device__ __forceinline__ void cp_wait() {
    asm volatile("cp.async.wait_group %0;\n" :: "n"(N));
}
__device__ __forceinline__ float ex2f(float x) {
    float y; asm("ex2.approx.f32 %0, %1;" : "=f"(y) : "f"(x)); return y;
}
__device__ __forceinline__ float lg2f(float x) {
    float y; asm("lg2.approx.f32 %0, %1;" : "=f"(y) : "f"(x)); return y;
}
__device__ __forceinline__ __half2 pack_h2(float x1, float x2) {
    unsigned p;
    asm("cvt.rn.f16x2.f32 %0, %1, %2;" : "=r"(p) : "f"(x2), "f"(x1));
    return *reinterpret_cast<__half2*>(&p);
}
__device__ __forceinline__ __half2 ex2_h2(__half2 ph) {
    unsigned p = *reinterpret_cast<unsigned*>(&ph);
    unsigned e;
    asm("ex2.approx.f16x2 %0, %1;" : "=r"(e) : "r"(p));
    return *reinterpret_cast<__half2*>(&e);
}

__global__ __launch_bounds__(NTH, 2)
void viterbi_split_kernel(const float* __restrict__ scores,
                          const int* __restrict__ targets,
                          const int* __restrict__ lengths,
                          float* __restrict__ out) {
    __shared__ __align__(16) float raw[4][KK];   // quad-buffered raw tiles (40 KB)
    __shared__ float red2[4][64];                // per-group partial sums
    __shared__ float vbuf[64];                   // shifted log2 state vector
    __shared__ float r0s[2];                     // stale anchor, double buffered
    __shared__ float mxi[2];                     // init warp maxes
    __shared__ int   tg[TT];
    __shared__ int   sPair, sFin;
    __shared__ float sa[4], sg[4];

    const int bx   = blockIdx.x;
    const int dirB = bx >> 7;            // 0 = forward, 1 = backward
    const int b    = bx & (BB - 1);
    const int tid  = threadIdx.x;
    const int lane = tid & 31;
    const int wid  = tid >> 5;
    const int g    = tid >> 6;           // group 0..3
    const int c    = tid & 63;           // output tag index, active < 50
    const int len  = lengths[b];
    const int m    = (len + 1) >> 1;
    const int nv   = dirB ? (len - m + 1) : m;   // visits incl. bwd virtual visit 0
    const float* base = scores + (size_t)b * TT * KK;
    const float L = 1.4426950408889634f; // log2(e)
    const __half2 clamp12 = __float2half2_rn(12.0f);

    tg[tid] = targets[b * TT + tid];

    auto issue = [&](int vv) {
        bool real = (vv < nv) && (!dirB || vv >= 1);
        if (real) {
            int t = dirB ? (len - vv) : vv;
            const float4* src = (const float4*)(base + (size_t)t * KK);
            float4* dst = (float4*)raw[vv & 3];
            #pragma unroll
            for (int i = 0; i < 3; ++i) {
                int c4 = tid + i * NTH;
                if (c4 < 625) cp16(dst + c4, src + c4);
            }
        }
        cp_commit();                     // always commit: static group accounting
    };

    issue(0); issue(1); issue(2); issue(3);
    cp_wait<3>();
    __syncthreads();                     // visit 0 certified

    float gold = 0.f, r = 0.f, shift = 0.f, dcur = 0.f;

    // ---- init state at the starting end ----
    if (!dirB) {
        if (tid < 64) {
            r = (c < KDIM) ? raw[0][START_TAG * KDIM + c] * L : -1e30f;
            float mw = r;
            #pragma unroll
            for (int o = 16; o > 0; o >>= 1)
                mw = fmaxf(mw, __shfl_xor_sync(0xFFFFFFFFu, mw, o));
            if (lane == 0) mxi[wid] = mw;
        }
        if (tid == 0) gold += raw[0][tg[0]];
    } else {
        if (tid < 64) r = (c == END_TAG) ? 0.f : -1e30f;
    }
    __syncthreads();                     // mxi visible
    if (!dirB) {
        dcur = fmaxf(mxi[0], mxi[1]) + SLACK;   // exact-max anchor at init
        if (tid < 64) {
            vbuf[c] = (c < KDIM) ? (r - dcur) : -1e30f;
            if (c == 0) r0s[0] = r;
        }
    } else {
        dcur = 0.f;                       // beta init: max is exactly 0 (END tag)
        if (tid < 64) {
            vbuf[c] = r;
            if (c == 0) r0s[0] = 0.f;
        }
    }

    for (int v = 1; v < nv; ++v) {
        cp_wait<2>();                    // own chunks of visit v landed
        __syncthreads();                 // barA: tile v + vbuf certified
        issue(v + 3);                    // into slot (v-1)&3 (drained)

        const float* sb = raw[v & 3];
        const int t = dirB ? (len - v) : v;
        if (tid == 0) gold += sb[tg[t]];

        if (c < KDIM) {
            const float* ab = vbuf;
            __half2 acc0 = __float2half2_rn(0.f);
            __half2 acc1 = __float2half2_rn(0.f);
            // 7 packed pairs cover i = 0..13 (i=13 virtual: ab[g+52] = -1e30 -> 0)
            #pragma unroll
            for (int p = 0; p < 7; ++p) {
                int i1 = 2 * p, i2 = 2 * p + 1;
                int j1 = g + 4 * i1, j2 = g + 4 * i2;
                int jj1 = (j1 < KDIM) ? j1 : 0;
                int jj2 = (j2 < KDIM) ? j2 : 0;
                float x1, x2;
                if (!dirB) {             // fwd: addr j*50 + c
                    x1 = __fmaf_rn(sb[jj1 * KDIM + c], L, ab[j1]);
                    x2 = __fmaf_rn(sb[jj2 * KDIM + c], L, ab[j2]);
                } else {                 // bwd: addr c*50 + k
                    x1 = __fmaf_rn(sb[c * KDIM + jj1], L, ab[j1]);
                    x2 = __fmaf_rn(sb[c * KDIM + jj2], L, ab[j2]);
                }
                __half2 e = ex2_h2(__hmin2(pack_h2(x1, x2), clamp12));
                if (p & 1) acc1 = __hadd2(acc1, e);
                else       acc0 = __hadd2(acc0, e);
            }
            float2 f0 = __half22float2(acc0);
            float2 f1 = __half22float2(acc1);
            red2[g][c] = (f0.x + f1.x) + (f0.y + f1.y);
        }
        __syncthreads();                 // barB: red2 ready, vbuf free

        if (tid < 64 && c < KDIM) {      // serial g0 tail (2 warps)
            float tot = red2[0][c] + red2[1][c] + red2[2][c] + red2[3][c];
            r = lg2f(fmaxf(tot, 1e-35f));           // guard: never -inf
            shift += dcur;
            float dn = r0s[(v - 1) & 1] + SLACK;    // stale anchor r_{v-1}[0]
            vbuf[c] = r - dn;
            dcur = dn;
            if (c == 0) r0s[v & 1] = r;
        }
    }

    cp_wait<0>();
    __syncthreads();

    // ---- publish half-result ----
    if (tid < 64 && c < KDIM) g_vec[dirB][b][c] = r + shift;   // absolute log2
    if (tid == 0) g_gold[dirB][b] = gold;
    __syncthreads();
    if (tid == 0) {
        __threadfence();
        sPair = atomicAdd(&g_pair[b], 1);
    }
    __syncthreads();

    if (sPair == 1) {                    // second arrival: combine the pair
        __threadfence();
        if (tid < 32) {
            int j2 = tid + 32;
            float x1 = g_vec[0][b][tid] + g_vec[1][b][tid];
            float x2 = (j2 < KDIM) ? (g_vec[0][b][j2] + g_vec[1][b][j2]) : -1e30f;
            float mx = fmaxf(x1, x2);
            #pragma unroll
            for (int o = 16; o > 0; o >>= 1)
                mx = fmaxf(mx, __shfl_xor_sync(0xFFFFFFFFu, mx, o));
            float s = ex2f(x1 - mx) + ex2f(x2 - mx);
            #pragma unroll
            for (int o = 16; o > 0; o >>= 1)
                s += __shfl_xor_sync(0xFFFFFFFFu, s, o);
            if (tid == 0) {
                g_apart[b] = (mx + lg2f(s)) * 0.6931471805599453f;
                g_gpart[b] = g_gold[0][b] + g_gold[1][b];
                g_pair[b]  = 0;          // reset for next graph replay
            }
        }
    }
    __syncthreads();
    if (tid == 0) {
        __threadfence();
        int old = atomicAdd(&g_count, 1);
        sFin = (old == 2 * BB - 1) ? 1 : 0;
    }
    __syncthreads();

    if (sFin) {                          // very last CTA: deterministic final reduce
        __threadfence();
        float a = 0.f, gd = 0.f;
        if (tid < BB) { a = g_apart[tid]; gd = g_gpart[tid]; }
        #pragma unroll
        for (int o = 16; o > 0; o >>= 1) {
            a  += __shfl_down_sync(0xFFFFFFFFu, a, o);
            gd += __shfl_down_sync(0xFFFFFFFFu, gd, o);
        }
        if (tid < BB && lane == 0) { sa[wid] = a; sg[wid] = gd; }
        __syncthreads();
        if (tid == 0) {
            float A = sa[0] + sa[1] + sa[2] + sa[3];
            float G = sg[0] + sg[1] + sg[2] + sg[3];
            out[0] = (A - G) / (float)BB;
            atomicExch(&g_count, 0);     // reset for next graph replay
        }
    }
}

extern "C" void kernel_launch(void* const* d_in, const int* in_sizes, int n_in,
                              void* d_out, int out_size) {
    const float* scores  = (const float*)d_in[0];
    const int*   targets = (const int*)d_in[1];
    const int*   lengths = (const int*)d_in[2];
    // d_in[3] = tmap_correct (unused scalar)
    viterbi_split_kernel<<<2 * BB, NTH>>>(scores, targets, lengths, (float*)d_out);
}

// round 9
// speedup vs baseline: 1.2738x; 1.2738x over previous
#include <cuda_runtime.h>
#include <cuda_fp16.h>

#define BB 128
#define TT 256
#define KDIM 50
#define KK 2500          // K*K
#define START_TAG 48
#define END_TAG 49
#define NTH 64
#define SLACK 4.0f       // steady-state exp2 args center at -SLACK (fp16-safe)

__device__ float g_vec[2][BB][64];   // [dir][seq][tag]: absolute log2 alpha/beta at split
__device__ float g_gold[2][BB];      // gold partial per (dir, seq)
__device__ float g_apart[BB];        // combined per-seq log all-paths (nats)
__device__ float g_gpart[BB];        // combined per-seq gold
__device__ int   g_pair[BB];         // per-pair arrival counters (self-resetting)
__device__ int   g_count = 0;        // global arrival counter (self-resetting)

__device__ __forceinline__ void cp16(void* dst_smem, const void* src) {
    unsigned s = (unsigned)__cvta_generic_to_shared(dst_smem);
    asm volatile("cp.async.cg.shared.global [%0], [%1], 16;\n" :: "r"(s), "l"(src));
}
__device__ __forceinline__ void cp_commit() {
    asm volatile("cp.async.commit_group;\n");
}
template <int N>
__device__ __forceinline__ void cp_wait() {
    asm volatile("cp.async.wait_group %0;\n" :: "n"(N));
}
__device__ __forceinline__ float ex2f(float x) {
    float y; asm("ex2.approx.f32 %0, %1;" : "=f"(y) : "f"(x)); return y;
}
__device__ __forceinline__ float lg2f(float x) {
    float y; asm("lg2.approx.f32 %0, %1;" : "=f"(y) : "f"(x)); return y;
}
__device__ __forceinline__ __half2 pack_h2(float x1, float x2) {
    unsigned p;
    asm("cvt.rn.f16x2.f32 %0, %1, %2;" : "=r"(p) : "f"(x2), "f"(x1));
    return *reinterpret_cast<__half2*>(&p);
}
__device__ __forceinline__ __half2 ex2_h2(__half2 ph) {
    unsigned p = *reinterpret_cast<unsigned*>(&ph);
    unsigned e;
    asm("ex2.approx.f16x2 %0, %1;" : "=r"(e) : "r"(p));
    return *reinterpret_cast<__half2*>(&e);
}

__global__ __launch_bounds__(NTH, 2)
void viterbi_col_kernel(const float* __restrict__ scores,
                        const int* __restrict__ targets,
                        const int* __restrict__ lengths,
                        float* __restrict__ out) {
    __shared__ __align__(16) float raw[4][KK];   // quad-buffered raw tiles (40 KB)
    __shared__ float vbuf[64];                   // shifted log2 state vector
    __shared__ float r0s[2];                     // stale anchor, double buffered
    __shared__ float mxi[2];                     // init warp maxes
    __shared__ int   tg[TT];
    __shared__ int   sPair, sFin;
    __shared__ float sa[2], sg[2];

    const int bx   = blockIdx.x;
    const int dirB = bx >> 7;            // 0 = forward, 1 = backward
    const int b    = bx & (BB - 1);
    const int tid  = threadIdx.x;
    const int lane = tid & 31;
    const int wid  = tid >> 5;
    const int c    = tid;                // output tag column (active < 50)
    const int len  = lengths[b];
    const int m    = (len + 1) >> 1;
    const int nv   = dirB ? (len - m + 1) : m;   // visits incl. bwd virtual visit 0
    const float* base = scores + (size_t)b * TT * KK;
    const float L = 1.4426950408889634f; // log2(e)
    const __half2 clamp12 = __float2half2_rn(12.0f);
    const bool act = (c < KDIM);

    #pragma unroll
    for (int i = 0; i < 4; ++i) tg[tid + i * NTH] = targets[b * TT + tid + i * NTH];

    auto issue = [&](int vv) {
        bool real = (vv < nv) && (!dirB || vv >= 1);
        if (real) {
            int t = dirB ? (len - vv) : vv;
            const float4* src = (const float4*)(base + (size_t)t * KK);
            float4* dst = (float4*)raw[vv & 3];
            #pragma unroll
            for (int i = 0; i < 10; ++i) {
                int c4 = tid + i * NTH;
                if (c4 < 625) cp16(dst + c4, src + c4);
            }
        }
        cp_commit();                     // always commit: static group accounting
    };

    issue(0); issue(1); issue(2); issue(3);
    cp_wait<3>();
    __syncthreads();                     // visit 0 certified

    float gold = 0.f, r = 0.f, shift = 0.f, dcur = 0.f;

    // ---- init state at the starting end ----
    if (!dirB) {
        r = act ? raw[0][START_TAG * KDIM + c] * L : -1e30f;
        float mw = r;
        #pragma unroll
        for (int o = 16; o > 0; o >>= 1)
            mw = fmaxf(mw, __shfl_xor_sync(0xFFFFFFFFu, mw, o));
        if (lane == 0) mxi[wid] = mw;
        if (tid == 0) gold += raw[0][tg[0]];
    } else {
        r = (c == END_TAG) ? 0.f : -1e30f;
    }
    __syncthreads();                     // mxi visible
    if (!dirB) {
        dcur = fmaxf(mxi[0], mxi[1]) + SLACK;   // exact-max anchor at init
        vbuf[c] = act ? (r - dcur) : -1e30f;
        if (c == 0) r0s[0] = r;
    } else {
        dcur = 0.f;
        vbuf[c] = r;
        if (c == 0) r0s[0] = 0.f;
    }

    for (int v = 1; v < nv; ++v) {
        cp_wait<2>();                    // tile v landed
        __syncthreads();                 // SINGLE barrier: tile v + vbuf certified
        issue(v + 3);                    // into slot (v-1)&3 (fully drained)

        const float* sb = raw[v & 3];
        const int t = dirB ? (len - v) : v;
        if (tid == 0) gold += sb[tg[t]];

        if (act) {
            const float* ab = vbuf;
            __half2 acc0 = __float2half2_rn(0.f);
            __half2 acc1 = __float2half2_rn(0.f);
            if (!dirB) {                 // fwd: addr j*50 + c (column access)
                #pragma unroll
                for (int p = 0; p < 25; ++p) {
                    int j = 2 * p;
                    float x1 = __fmaf_rn(sb[j * KDIM + c],       L, ab[j]);
                    float x2 = __fmaf_rn(sb[(j + 1) * KDIM + c], L, ab[j + 1]);
                    __half2 e = ex2_h2(__hmin2(pack_h2(x1, x2), clamp12));
                    if (p & 1) acc1 = __hadd2(acc1, e);
                    else       acc0 = __hadd2(acc0, e);
                }
            } else {                     // bwd: addr c*50 + k (row access, float2)
                const float2* row = (const float2*)(sb + c * KDIM);
                #pragma unroll
                for (int p = 0; p < 25; ++p) {
                    float2 sv = row[p];
                    int j = 2 * p;
                    float x1 = __fmaf_rn(sv.x, L, ab[j]);
                    float x2 = __fmaf_rn(sv.y, L, ab[j + 1]);
                    __half2 e = ex2_h2(__hmin2(pack_h2(x1, x2), clamp12));
                    if (p & 1) acc1 = __hadd2(acc1, e);
                    else       acc0 = __hadd2(acc0, e);
                }
            }
            float2 f0 = __half22float2(acc0);
            float2 f1 = __half22float2(acc1);
            float tot = (f0.x + f1.x) + (f0.y + f1.y);
            r = lg2f(fmaxf(tot, 1e-35f));           // never -inf
            shift += dcur;
            float dn = r0s[(v - 1) & 1] + SLACK;    // stale anchor r_{v-1}[0]
            vbuf[c] = r - dn;
            dcur = dn;
            if (c == 0) r0s[v & 1] = r;
        }
    }

    cp_wait<0>();
    __syncthreads();

    // ---- publish half-result ----
    if (act) g_vec[dirB][b][c] = r + shift;   // absolute log2
    if (tid == 0) g_gold[dirB][b] = gold;
    __syncthreads();
    if (tid == 0) {
        __threadfence();
        sPair = atomicAdd(&g_pair[b], 1);
    }
    __syncthreads();

    if (sPair == 1) {                    // second arrival: combine the pair
        __threadfence();
        if (tid < 32) {
            int j2 = tid + 32;
            float x1 = g_vec[0][b][tid] + g_vec[1][b][tid];
            float x2 = (j2 < KDIM) ? (g_vec[0][b][j2] + g_vec[1][b][j2]) : -1e30f;
            float mx = fmaxf(x1, x2);
            #pragma unroll
            for (int o = 16; o > 0; o >>= 1)
                mx = fmaxf(mx, __shfl_xor_sync(0xFFFFFFFFu, mx, o));
            float s = ex2f(x1 - mx) + ex2f(x2 - mx);
            #pragma unroll
            for (int o = 16; o > 0; o >>= 1)
                s += __shfl_xor_sync(0xFFFFFFFFu, s, o);
            if (tid == 0) {
                g_apart[b] = (mx + lg2f(s)) * 0.6931471805599453f;
                g_gpart[b] = g_gold[0][b] + g_gold[1][b];
                g_pair[b]  = 0;          // reset for next graph replay
            }
        }
    }
    __syncthreads();
    if (tid == 0) {
        __threadfence();
        int old = atomicAdd(&g_count, 1);
        sFin = (old == 2 * BB - 1) ? 1 : 0;
    }
    __syncthreads();

    if (sFin) {                          // very last CTA: deterministic final reduce
        __threadfence();
        float a  = g_apart[tid] + g_apart[tid + 64];
        float gd = g_gpart[tid] + g_gpart[tid + 64];
        #pragma unroll
        for (int o = 16; o > 0; o >>= 1) {
            a  += __shfl_down_sync(0xFFFFFFFFu, a, o);
            gd += __shfl_down_sync(0xFFFFFFFFu, gd, o);
        }
        if (lane == 0) { sa[wid] = a; sg[wid] = gd; }
        __syncthreads();
        if (tid == 0) {
            out[0] = ((sa[0] + sa[1]) - (sg[0] + sg[1])) / (float)BB;
            atomicExch(&g_count, 0);     // reset for next graph replay
        }
    }
}

extern "C" void kernel_launch(void* const* d_in, const int* in_sizes, int n_in,
                              void* d_out, int out_size) {
    const float* scores  = (const float*)d_in[0];
    const int*   targets = (const int*)d_in[1];
    const int*   lengths = (const int*)d_in[2];
    // d_in[3] = tmap_correct (unused scalar)
    viterbi_col_kernel<<<2 * BB, NTH>>>(scores, targets, lengths, (float*)d_out);
}